// round 1
// baseline (speedup 1.0000x reference)
#include <cuda_runtime.h>

// Ray-marched volumetric sphere, 1024x1024 pixels.
// in[0] = scene (4 f32: cx, cy, cz, radius)
// in[1] = dirs  (1024*1024*3 f32, normalized ray directions)
// out   = pixels (1024*1024*3 f32)

#define MAX_STEPS   12
#define BASE_STEP   0.2f
#define ABSORPTION  0.1f
#define SCATTERING  0.1f
#define DENSITY     6.0f
#define SIGMA       (SCATTERING + ABSORPTION + 0.4f)   // 0.6
#define LIGHT_K     (DENSITY * (SCATTERING + ABSORPTION))  // 1.2

__device__ __forceinline__ float fsqrt_approx(float x) {
    float r;
    asm("sqrt.approx.f32 %0, %1;" : "=f"(r) : "f"(x));
    return r;
}

__global__ __launch_bounds__(256) void raymarch_kernel(
    const float* __restrict__ scene,
    const float* __restrict__ dirs,
    float* __restrict__ out,
    int n)
{
    const int i = blockIdx.x * 256 + threadIdx.x;
    if (i >= n) return;

    // Scene (uniform; hits L2/L1 after first warp)
    const float cx = __ldg(scene + 0);
    const float cy = __ldg(scene + 1);
    const float cz = __ldg(scene + 2);
    const float radius = __ldg(scene + 3);

    // RO = (0, 0, 3)
    const float ocx = 0.0f - cx;
    const float ocy = 0.0f - cy;
    const float ocz = 3.0f - cz;

    const float rdx = dirs[3 * i + 0];
    const float rdy = dirs[3 * i + 1];
    const float rdz = dirs[3 * i + 2];

    const float a = rdx * rdx + rdy * rdy + rdz * rdz;
    const float b = 2.0f * (rdx * ocx + rdy * ocy + rdz * ocz);
    const float c = (ocx * ocx + ocy * ocy + ocz * ocz) - radius * radius;
    const float disc = b * b - 4.0f * a * c;

    const float sq = fsqrt_approx(disc > 0.0f ? disc : 1.0f);
    const float inv2a = 0.5f / a;
    const float x1 = (-b - sq) * inv2a;
    const float x2 = (-b + sq) * inv2a;
    const bool hit = (disc >= 0.0f) && (x2 >= 0.0f);

    // Background
    float px = 0.572f, py = 0.772f, pz = 0.921f;

    if (hit) {
        const float t0 = fmaxf(x1, 0.0f);
        const float t1 = x2;
        const float seg = t1 - t0;
        const float ns = ceilf(seg / BASE_STEP);
        const float ns_safe = fmaxf(ns, 1.0f);
        const float step = seg / ns_safe;

        const int nsi = min((int)ns, MAX_STEPS);

        const float r2 = radius * radius;
        float acc = 0.0f;
        #pragma unroll 4
        for (int k = 0; k < nsi; k++) {
            const float t = t1 - ((float)k + 0.5f) * step;
            // p = RO + t*rd; pc = p - center
            const float pcx = ocx + t * rdx;
            const float pcy = ocy + t * rdy;
            const float pcz = ocz + t * rdz;
            const float lb = 2.0f * pcy;
            const float lc = pcx * pcx + pcy * pcy + pcz * pcz - r2;
            const float ld = lb * lb - 4.0f * lc;
            const float lsq = fsqrt_approx(ld > 0.0f ? ld : 1.0f);
            const float vt1 = (-lb + lsq) * 0.5f;
            if (ld >= 0.0f && vt1 >= 0.0f) {
                acc += __expf(-LIGHT_K * vt1);
            }
        }

        // transparency = s**ns          = exp(-SIGMA*step*ns)
        // s**(ns+1)                     = exp(-SIGMA*step*(ns+1))
        const float st = SIGMA * step;
        const float transparency = __expf(-st * ns);
        const float result = SCATTERING * DENSITY * step * __expf(-st * (ns + 1.0f)) * acc;

        px = 0.572f * transparency + 1.3f * result;
        py = 0.772f * transparency + 0.3f * result;
        pz = 0.921f * transparency + 0.9f * result;
    }

    out[3 * i + 0] = px;
    out[3 * i + 1] = py;
    out[3 * i + 2] = pz;
}

extern "C" void kernel_launch(void* const* d_in, const int* in_sizes, int n_in,
                              void* d_out, int out_size) {
    const float* scene = (const float*)d_in[0];
    const float* dirs  = (const float*)d_in[1];
    float* out = (float*)d_out;
    const int n = in_sizes[1] / 3;   // number of pixels
    const int threads = 256;
    const int blocks = (n + threads - 1) / threads;
    raymarch_kernel<<<blocks, threads>>>(scene, dirs, out, n);
}

// round 6
// speedup vs baseline: 1.1599x; 1.1599x over previous
#include <cuda_runtime.h>

// Ray-marched volumetric sphere, 1024x1024 pixels, 4 pixels per thread.
// in[0] = scene (4 f32: cx, cy, cz, radius)
// in[1] = dirs  (1024*1024*3 f32, normalized ray directions)
// out   = pixels (1024*1024*3 f32)

#define MAX_STEPS   12
#define LOG2E       1.4426950408889634f
#define K_LIGHT     (-1.2f * LOG2E)      // exponent coeff for light attenuation (exp2)
#define K_SIGMA     (-0.6f * LOG2E)      // exponent coeff for transparency (exp2)

__device__ __forceinline__ float fsqrt_approx(float x) {
    float r;
    asm("sqrt.approx.f32 %0, %1;" : "=f"(r) : "f"(x));
    return r;
}
__device__ __forceinline__ float fexp2_approx(float x) {
    float r;
    asm("ex2.approx.f32 %0, %1;" : "=f"(r) : "f"(x));
    return r;
}

// Returns transparency T and scatter R for one pixel.
__device__ __forceinline__ void shade(
    float rdx, float rdy, float rdz,
    float ocx, float ocy, float ocz, float r2,
    float& T, float& R)
{
    // a = |rd|^2 == 1 (dirs normalized). Half-b quadratic form:
    // x = -hb +- sqrt(hb^2 - c)
    const float hb = rdx * ocx + rdy * ocy + rdz * ocz;
    const float c  = ocx * ocx + ocy * ocy + ocz * ocz - r2;
    const float disc = hb * hb - c;

    T = 1.0f; R = 0.0f;
    if (disc < 0.0f) return;

    const float sq = fsqrt_approx(disc);
    const float x2 = sq - hb;
    if (x2 < 0.0f) return;

    const float x1 = -sq - hb;
    const float t0 = fmaxf(x1, 0.0f);
    const float seg = x2 - t0;
    const float ns = ceilf(seg * 5.0f);          // seg / 0.2
    const float ns_safe = fmaxf(ns, 1.0f);
    const float step = __fdividef(seg, ns_safe);
    const int nsi = min((int)ns, MAX_STEPS);

    // March from t1 backwards: pc_k = oc + (x2 - (k+0.5)*step)*rd
    // Incremental update: pc -= step*rd each iteration.
    const float tinit = x2 - 0.5f * step;
    float pcx = ocx + tinit * rdx;
    float pcy = ocy + tinit * rdy;
    float pcz = ocz + tinit * rdz;
    const float dx = step * rdx;
    const float dy = step * rdy;
    const float dz = step * rdz;

    // ld = lb^2 - 4*lc = 4*(r2 - pcx^2 - pcz^2) = 4*h
    // lsq = 2*sqrt(h)  (dummy: sqrt(0.25)=0.5 matches reference sqrt(1)/2)
    // vt1 = sqrt(h) - pcy
    float acc = 0.0f;
    #pragma unroll 4
    for (int k = 0; k < nsi; k++) {
        float h = r2 - pcx * pcx;
        h = h - pcz * pcz;
        const float hs = (h > 0.0f) ? h : 0.25f;
        const float shq = fsqrt_approx(hs);
        const float vt1 = shq - pcy;
        const float e = fexp2_approx(K_LIGHT * vt1);
        if ((h >= 0.0f) && (vt1 >= 0.0f)) acc += e;
        pcx -= dx; pcy -= dy; pcz -= dz;
    }

    // T = exp(-0.6*step*ns);  R = 0.6*step * T * exp(-0.6*step) * acc
    const float ks = K_SIGMA * step;
    T = fexp2_approx(ks * ns);
    R = 0.6f * step * T * fexp2_approx(ks) * acc;
}

__global__ __launch_bounds__(256) void raymarch_kernel(
    const float* __restrict__ scene,
    const float4* __restrict__ dirs4,
    float4* __restrict__ out4,
    int nthreads)
{
    const int t = blockIdx.x * 256 + threadIdx.x;
    if (t >= nthreads) return;

    const float cx = __ldg(scene + 0);
    const float cy = __ldg(scene + 1);
    const float cz = __ldg(scene + 2);
    const float radius = __ldg(scene + 3);
    const float r2 = radius * radius;

    // RO = (0, 0, 3)
    const float ocx = 0.0f - cx;
    const float ocy = 0.0f - cy;
    const float ocz = 3.0f - cz;

    // 4 pixels = 12 floats = 3 float4
    const float4 d0 = dirs4[3 * t + 0];
    const float4 d1 = dirs4[3 * t + 1];
    const float4 d2 = dirs4[3 * t + 2];

    float T0, R0, T1, R1, T2, R2, T3, R3;
    shade(d0.x, d0.y, d0.z, ocx, ocy, ocz, r2, T0, R0);
    shade(d0.w, d1.x, d1.y, ocx, ocy, ocz, r2, T1, R1);
    shade(d1.z, d1.w, d2.x, ocx, ocy, ocz, r2, T2, R2);
    shade(d2.y, d2.z, d2.w, ocx, ocy, ocz, r2, T3, R3);

    // color = BG*T + LIGHT*R   (BG=(0.572,0.772,0.921), LIGHT=(1.3,0.3,0.9))
    float4 o0, o1, o2;
    o0.x = 0.572f * T0 + 1.3f * R0;
    o0.y = 0.772f * T0 + 0.3f * R0;
    o0.z = 0.921f * T0 + 0.9f * R0;
    o0.w = 0.572f * T1 + 1.3f * R1;
    o1.x = 0.772f * T1 + 0.3f * R1;
    o1.y = 0.921f * T1 + 0.9f * R1;
    o1.z = 0.572f * T2 + 1.3f * R2;
    o1.w = 0.772f * T2 + 0.3f * R2;
    o2.x = 0.921f * T2 + 0.9f * R2;
    o2.y = 0.572f * T3 + 1.3f * R3;
    o2.z = 0.772f * T3 + 0.3f * R3;
    o2.w = 0.921f * T3 + 0.9f * R3;

    out4[3 * t + 0] = o0;
    out4[3 * t + 1] = o1;
    out4[3 * t + 2] = o2;
}

extern "C" void kernel_launch(void* const* d_in, const int* in_sizes, int n_in,
                              void* d_out, int out_size) {
    const float* scene = (const float*)d_in[0];
    const float4* dirs4 = (const float4*)d_in[1];
    float4* out4 = (float4*)d_out;
    const int npix = in_sizes[1] / 3;
    const int nthreads = npix / 4;          // 4 pixels per thread
    const int threads = 256;
    const int blocks = (nthreads + threads - 1) / threads;
    raymarch_kernel<<<blocks, threads>>>(scene, dirs4, out4, nthreads);
}